// round 9
// baseline (speedup 1.0000x reference)
#include <cuda_runtime.h>
#include <cuda_fp16.h>
#include <mma.h>
#include <math.h>

using namespace nvcuda;

#define NN 100000
#define EE 1600000
#define HH 64
#define XS_LD 80   // padded smem stride (halves / floats)

typedef unsigned long long u64;

// ---------------- scratch (device globals) ----------------------------------
__device__ __half g_y[2 * (size_t)NN * HH];   // layer-1 GEMM outputs (fp16)
__device__ __half g_y2[2 * (size_t)NN * HH];  // layer-2 GEMM outputs (fp16)
__device__ float  g_norms[4 * NN];            // csp | cdp | csn | cdn
__device__ int    g_cnt[4 * NN];              // int degree counts (same layout)
__device__ int    g_off[2 * (NN + 1)];        // CSR row offsets (dst) per relation
__device__ int    g_cur[2 * NN];              // scatter cursors
__device__ int    g_csr[2 * EE];              // src ids grouped by dst
__device__ int    g_flag[2 * 128];            // lookback flags (0/1/2)
__device__ int    g_pval[2 * 128];            // block partial sums
__device__ int    g_ival[2 * 128];            // block inclusive prefixes
__device__ float  g_proj[4 * NN];             // classifier projections [N][4]

// ---------------- utility ----------------------------------------------------
// zero cnt (n int4 worth = 4n ints) and the 2*128 lookback flags
__global__ void zero_kernel(int4* __restrict__ cnt4, int* __restrict__ flag, int n) {
    int t = blockIdx.x * blockDim.x + threadIdx.x;
    if (t < n) cnt4[t] = make_int4(0, 0, 0, 0);
    else if (t < n + 256) flag[t - n] = 0;
}

__global__ void deg4_kernel(const int* __restrict__ sp, const int* __restrict__ dp,
                            const int* __restrict__ sn, const int* __restrict__ dn,
                            int* __restrict__ cnt, int n, int nE) {
    int t = blockIdx.x * blockDim.x + threadIdx.x;
    if (t >= nE) return;
    int w = blockIdx.y;
    const int* idx = (w == 0) ? sp : (w == 1) ? dp : (w == 2) ? sn : dn;
    atomicAdd(cnt + (size_t)w * n + idx[t], 1);
}

// ---------------- one-launch scan: norms (all 4) + CSR offsets (lookback) ----
__global__ void scan_lb_norm(const int* __restrict__ cnt, float* __restrict__ norms,
                             volatile int* flag, volatile int* pval, volatile int* ival,
                             int* __restrict__ offv, int* __restrict__ cur,
                             int n, int nEp, int nEn) {
    int w = blockIdx.y;                 // 0..3
    int bx = blockIdx.x;
    int tid = threadIdx.x;
    const int* c = cnt + (size_t)w * n;
    float* nm = norms + (size_t)w * n;
    int base = bx * 1024 + tid * 4;

    int v[4], s = 0;
    #pragma unroll
    for (int j = 0; j < 4; j++) {
        int i = base + j;
        v[j] = (i < n) ? c[i] : 0;
        s += v[j];
        if (i < n) nm[i] = (v[j] > 0) ? rsqrtf((float)v[j]) : 0.f;
    }
    if (!(w & 1)) return;               // only dst arrays build CSR
    int rel = w >> 1;
    int sbase = rel * 128;

    // block-wide inclusive scan of per-thread sums
    __shared__ int sm[256];
    sm[tid] = s; __syncthreads();
    for (int ofs = 1; ofs < 256; ofs <<= 1) {
        int a = (tid >= ofs) ? sm[tid - ofs] : 0;
        __syncthreads();
        sm[tid] += a;
        __syncthreads();
    }
    int excl = sm[tid] - s;
    int bsum = sm[255];

    // decoupled lookback (thread 0)
    __shared__ int bprefix;
    if (tid == 0) {
        pval[sbase + bx] = bsum;
        __threadfence();
        flag[sbase + bx] = 1;
        int pref = 0;
        for (int p = bx - 1; p >= 0; ) {
            int f;
            do { f = flag[sbase + p]; } while (f == 0);
            if (f == 2) { pref += ival[sbase + p]; break; }
            pref += pval[sbase + p];
            p--;
        }
        ival[sbase + bx] = pref + bsum;
        __threadfence();
        flag[sbase + bx] = 2;
        bprefix = pref;
    }
    __syncthreads();

    int ex = bprefix + excl;
    int* o  = offv + (size_t)rel * (n + 1);
    int* cu = cur + (size_t)rel * n;
    #pragma unroll
    for (int j = 0; j < 4; j++) {
        int i = base + j;
        if (i < n) { o[i] = ex; cu[i] = ex; }
        ex += v[j];
    }
    if (bx == 0 && tid == 0) o[n] = rel ? nEn : nEp;
}

// ---------------- wmma GEMM body (layer 1, fp32 input) -----------------------
__device__ __forceinline__ void gemm_body_f32(const float* __restrict__ X,
                                              const float* __restrict__ cs,
                                              const float* __restrict__ W,
                                              __half* __restrict__ Yo, int n, int blk) {
    __shared__ __half Wh[64 * XS_LD];
    __shared__ __half Xh[128 * XS_LD];
    __shared__ float  Os[128 * XS_LD];
    int tid = threadIdx.x;
    int row0 = blk * 128;

    for (int i = tid; i < 2048; i += 256) {
        int k = i >> 5, j = i & 31;
        float2 v = ((const float2*)W)[(size_t)k * 32 + j];
        *(__half2*)&Wh[k * XS_LD + 2 * j] = __floats2half2_rn(v.x, v.y);
    }
    for (int i = tid; i < 2048; i += 256) {
        int r = i >> 4, kq = i & 15;
        int gr = row0 + r;
        float4 v = (gr < n) ? ((const float4*)X)[(size_t)gr * 16 + kq]
                            : make_float4(0.f, 0.f, 0.f, 0.f);
        *(__half2*)&Xh[r * XS_LD + 4 * kq + 0] = __floats2half2_rn(v.x, v.y);
        *(__half2*)&Xh[r * XS_LD + 4 * kq + 2] = __floats2half2_rn(v.z, v.w);
    }
    __syncthreads();

    int w = tid >> 5;
    wmma::fragment<wmma::accumulator, 16, 16, 16, float> acc[4];
    #pragma unroll
    for (int t = 0; t < 4; t++) wmma::fill_fragment(acc[t], 0.f);
    #pragma unroll
    for (int k = 0; k < 64; k += 16) {
        wmma::fragment<wmma::matrix_a, 16, 16, 16, __half, wmma::row_major> a;
        wmma::load_matrix_sync(a, &Xh[(w * 16) * XS_LD + k], XS_LD);
        #pragma unroll
        for (int t = 0; t < 4; t++) {
            wmma::fragment<wmma::matrix_b, 16, 16, 16, __half, wmma::row_major> b;
            wmma::load_matrix_sync(b, &Wh[k * XS_LD + t * 16], XS_LD);
            wmma::mma_sync(acc[t], a, b, acc[t]);
        }
    }
    #pragma unroll
    for (int t = 0; t < 4; t++)
        wmma::store_matrix_sync(&Os[(w * 16) * XS_LD + t * 16], acc[t], XS_LD,
                                wmma::mem_row_major);
    __syncthreads();

    for (int i = tid; i < 2048; i += 256) {
        int r = i >> 4, q = i & 15;
        int gr = row0 + r;
        if (gr >= n) continue;
        float c = cs[gr];
        float4 v = *(const float4*)&Os[r * XS_LD + 4 * q];
        __half2 o[2] = {__floats2half2_rn(v.x * c, v.y * c),
                        __floats2half2_rn(v.z * c, v.w * c)};
        *(uint2*)(Yo + (size_t)gr * 64 + 4 * q) = *(const uint2*)o;
    }
}

// ---------------- fat kernel: layer-1 GEMM (both rels) + CSR scatter ---------
__global__ void __launch_bounds__(256)
gemm1_scatter(const float* __restrict__ x, const float* __restrict__ norms,
              const float* __restrict__ W0, const float* __restrict__ W1,
              __half* __restrict__ Y,
              const int* __restrict__ srcp, const int* __restrict__ dstp,
              const int* __restrict__ srcn, const int* __restrict__ dstn,
              int* __restrict__ cur, int* __restrict__ csr,
              int n, int nEp, int nEn, int gGemm, int gScat) {
    int b = blockIdx.x;
    if (b < 2 * gGemm) {
        int rel = b / gGemm;
        gemm_body_f32(x, norms + 2 * (size_t)rel * n,
                      rel ? W1 : W0, Y + (size_t)rel * n * 64, n, b % gGemm);
    } else {
        int sb = b - 2 * gGemm;
        int rel = sb / gScat;
        int e = (sb % gScat) * 256 + threadIdx.x;
        int nE = rel ? nEn : nEp;
        if (e >= nE) return;
        const int* src = rel ? srcn : srcp;
        const int* dst = rel ? dstn : dstp;
        int d = dst[e];
        int p = atomicAdd(cur + (size_t)rel * n + d, 1);
        csr[(size_t)rel * EE + p] = src[e];
    }
}

// ---------------- CSR pull (fp16 payload, fp32 accum, MLP=4) -----------------
__device__ __forceinline__ float2 csr_sum(const int* __restrict__ off,
                                          const int* __restrict__ csr,
                                          const __half2* __restrict__ ylane, int node) {
    int j = off[node], end = off[node + 1];
    float2 a0 = make_float2(0.f, 0.f), a1 = make_float2(0.f, 0.f);
    float2 a2 = make_float2(0.f, 0.f), a3 = make_float2(0.f, 0.f);
    for (; j + 4 <= end; j += 4) {
        int s0 = __ldg(csr + j + 0);
        int s1 = __ldg(csr + j + 1);
        int s2 = __ldg(csr + j + 2);
        int s3 = __ldg(csr + j + 3);
        __half2 h0 = __ldg(ylane + (size_t)s0 * 32);
        __half2 h1 = __ldg(ylane + (size_t)s1 * 32);
        __half2 h2 = __ldg(ylane + (size_t)s2 * 32);
        __half2 h3 = __ldg(ylane + (size_t)s3 * 32);
        float2 v0 = __half22float2(h0); a0.x += v0.x; a0.y += v0.y;
        float2 v1 = __half22float2(h1); a1.x += v1.x; a1.y += v1.y;
        float2 v2 = __half22float2(h2); a2.x += v2.x; a2.y += v2.y;
        float2 v3 = __half22float2(h3); a3.x += v3.x; a3.y += v3.y;
    }
    for (; j < end; j++) {
        int s = __ldg(csr + j);
        float2 v = __half22float2(__ldg(ylane + (size_t)s * 32));
        a0.x += v.x; a0.y += v.y;
    }
    a0.x += a1.x; a0.y += a1.y;
    a2.x += a3.x; a2.y += a3.y;
    a0.x += a2.x; a0.y += a2.y;
    return a0;
}

// ---------------- fused: layer-1 aggregation -> layer-2 GEMM -----------------
// block = 256 threads handles 128 nodes; warp aggregates 16 nodes into smem,
// then the block runs wmma with W1 and writes y2 (fp16).  y (input) != y2 (output)!
__global__ void __launch_bounds__(256)
agg1_gemm2(const __half* __restrict__ y, const int* __restrict__ off,
           const int* __restrict__ csr, const float* __restrict__ norms,
           const float* __restrict__ b0p, const float* __restrict__ b0n,
           const float* __restrict__ W1p, const float* __restrict__ W1n,
           __half* __restrict__ Yout, int n) {
    int rel = blockIdx.y;
    const float* cdst = norms + (size_t)(1 + 2 * rel) * n;
    const float* csrc = norms + (size_t)(2 * rel) * n;
    const float* b0 = rel ? b0n : b0p;
    const float* W  = rel ? W1n : W1p;
    const int* o    = off + (size_t)rel * (n + 1);
    const int* cs_  = csr + (size_t)rel * EE;
    const __half2* ybase = (const __half2*)(y + (size_t)rel * n * 64);
    __half* Yo = Yout + (size_t)rel * n * 64;

    __shared__ __half Wh[64 * XS_LD];
    __shared__ __half Xh[128 * XS_LD];
    __shared__ float  Os[128 * XS_LD];

    int tid = threadIdx.x, w = tid >> 5, lane = tid & 31;
    int row0 = blockIdx.x * 128;

    // stage W (fp32 -> fp16)
    for (int i = tid; i < 2048; i += 256) {
        int k = i >> 5, j = i & 31;
        float2 v = ((const float2*)W)[(size_t)k * 32 + j];
        *(__half2*)&Wh[k * XS_LD + 2 * j] = __floats2half2_rn(v.x, v.y);
    }

    float bxv = b0[2 * lane], byv = b0[2 * lane + 1];

    // aggregate 16 nodes per warp, relu-epilogue, write into Xh
    for (int i = 0; i < 16; i++) {
        int r = w * 16 + i;
        int node = row0 + r;
        __half2 hv;
        if (node < n) {
            float2 a = csr_sum(o, cs_, ybase + lane, node);
            float c = cdst[node];
            hv = __floats2half2_rn(fmaxf(c * a.x + bxv, 0.f),
                                   fmaxf(c * a.y + byv, 0.f));
        } else {
            hv = __floats2half2_rn(0.f, 0.f);
        }
        *(__half2*)&Xh[r * XS_LD + 2 * lane] = hv;
    }
    __syncthreads();

    // layer-2 MMA
    wmma::fragment<wmma::accumulator, 16, 16, 16, float> acc[4];
    #pragma unroll
    for (int t = 0; t < 4; t++) wmma::fill_fragment(acc[t], 0.f);
    #pragma unroll
    for (int k = 0; k < 64; k += 16) {
        wmma::fragment<wmma::matrix_a, 16, 16, 16, __half, wmma::row_major> a;
        wmma::load_matrix_sync(a, &Xh[(w * 16) * XS_LD + k], XS_LD);
        #pragma unroll
        for (int t = 0; t < 4; t++) {
            wmma::fragment<wmma::matrix_b, 16, 16, 16, __half, wmma::row_major> b;
            wmma::load_matrix_sync(b, &Wh[k * XS_LD + t * 16], XS_LD);
            wmma::mma_sync(acc[t], a, b, acc[t]);
        }
    }
    #pragma unroll
    for (int t = 0; t < 4; t++)
        wmma::store_matrix_sync(&Os[(w * 16) * XS_LD + t * 16], acc[t], XS_LD,
                                wmma::mem_row_major);
    __syncthreads();

    // epilogue: scale by c_src, write fp16
    for (int i = tid; i < 2048; i += 256) {
        int r = i >> 4, q = i & 15;
        int gr = row0 + r;
        if (gr >= n) continue;
        float c = csrc[gr];
        float4 v = *(const float4*)&Os[r * XS_LD + 4 * q];
        __half2 ov[2] = {__floats2half2_rn(v.x * c, v.y * c),
                         __floats2half2_rn(v.z * c, v.w * c)};
        *(uint2*)(Yo + (size_t)gr * 64 + 4 * q) = *(const uint2*)ov;
    }
}

// layer 2 agg fused: z = relu(cdp*sumP + b1p) - relu(cdn*sumN + b1n) + proj
__global__ void agg_l2(const __half* __restrict__ y, const int* __restrict__ off,
                       const int* __restrict__ csr, const float* __restrict__ norms,
                       const float* __restrict__ b1p, const float* __restrict__ b1n,
                       const float* __restrict__ Wc,
                       float* __restrict__ z, float* __restrict__ proj, int n) {
    __shared__ float Wcs[256];
    Wcs[threadIdx.x] = Wc[threadIdx.x];   // blockDim == 256
    __syncthreads();

    int node = blockIdx.x * 8 + (threadIdx.x >> 5);
    if (node >= n) return;
    int lane = threadIdx.x & 31;
    const __half2* ylP = (const __half2*)y + lane;
    const __half2* ylN = (const __half2*)(y + (size_t)n * 64) + lane;
    float2 aP = csr_sum(off, csr, ylP, node);
    float2 aN = csr_sum(off + (n + 1), csr + (size_t)EE, ylN, node);
    float cp = norms[(size_t)n + node];
    float cn = norms[3 * (size_t)n + node];
    float2 r;
    r.x = fmaxf(cp * aP.x + b1p[2 * lane + 0], 0.f) - fmaxf(cn * aN.x + b1n[2 * lane + 0], 0.f);
    r.y = fmaxf(cp * aP.y + b1p[2 * lane + 1], 0.f) - fmaxf(cn * aN.y + b1n[2 * lane + 1], 0.f);
    *(float2*)(z + (size_t)node * 64 + lane * 2) = r;

    int k = 2 * lane;
    float s0 = r.x * Wcs[k * 2 + 0] + r.y * Wcs[(k + 1) * 2 + 0];
    float s1 = r.x * Wcs[k * 2 + 1] + r.y * Wcs[(k + 1) * 2 + 1];
    float d0 = r.x * Wcs[128 + k * 2 + 0] + r.y * Wcs[128 + (k + 1) * 2 + 0];
    float d1 = r.x * Wcs[128 + k * 2 + 1] + r.y * Wcs[128 + (k + 1) * 2 + 1];
    #pragma unroll
    for (int o = 16; o > 0; o >>= 1) {
        s0 += __shfl_xor_sync(0xffffffffu, s0, o);
        s1 += __shfl_xor_sync(0xffffffffu, s1, o);
        d0 += __shfl_xor_sync(0xffffffffu, d0, o);
        d1 += __shfl_xor_sync(0xffffffffu, d1, o);
    }
    if (lane == 0) ((float4*)proj)[node] = make_float4(s0, s1, d0, d1);
}

// ---------------- classifier --------------------------------------------------
__global__ void cls_kernel(const float* __restrict__ p, const int* __restrict__ ei,
                           const float* __restrict__ bc, float* __restrict__ out, int nQ) {
    int q = blockIdx.x * blockDim.x + threadIdx.x;
    if (q >= nQ) return;
    int s = __ldg(ei + q);
    int d = __ldg(ei + nQ + q);
    float4 ps = ((const float4*)p)[s];
    float4 pd = ((const float4*)p)[d];
    float l0 = ps.x + pd.z + bc[0];
    float l1 = ps.y + pd.w + bc[1];
    float2 o;
    o.x = 1.f / (1.f + __expf(-l0));
    o.y = 1.f / (1.f + __expf(-l1));
    ((float2*)out)[q] = o;
}

// ---------------- launch -------------------------------------------------------
static inline int cdiv(long long a, int b) { return (int)((a + b - 1) / b); }

extern "C" void kernel_launch(void* const* d_in, const int* in_sizes, int n_in,
                              void* d_out, int out_size) {
    const float* x    = (const float*)d_in[0];
    const float* W0p  = (const float*)d_in[1];
    const float* b0p  = (const float*)d_in[2];
    const float* W0n  = (const float*)d_in[3];
    const float* b0n  = (const float*)d_in[4];
    const float* W1p  = (const float*)d_in[5];
    const float* b1p  = (const float*)d_in[6];
    const float* W1n  = (const float*)d_in[7];
    const float* b1n  = (const float*)d_in[8];
    const float* Wc   = (const float*)d_in[9];
    const float* bc   = (const float*)d_in[10];
    const int*   srcp = (const int*)d_in[11];
    const int*   dstp = (const int*)d_in[12];
    const int*   srcn = (const int*)d_in[13];
    const int*   dstn = (const int*)d_in[14];
    const int*   ei   = (const int*)d_in[15];

    const int n   = in_sizes[0] / HH;
    const int nEp = in_sizes[11];
    const int nEn = in_sizes[13];
    const int nQ  = in_sizes[15] / 2;

    __half *y, *y2;
    float *norms, *pbuf;
    int *cnt, *off, *cur, *csr, *flag, *pval, *ival;
    cudaGetSymbolAddress((void**)&y,     g_y);
    cudaGetSymbolAddress((void**)&y2,    g_y2);
    cudaGetSymbolAddress((void**)&norms, g_norms);
    cudaGetSymbolAddress((void**)&cnt,   g_cnt);
    cudaGetSymbolAddress((void**)&off,   g_off);
    cudaGetSymbolAddress((void**)&cur,   g_cur);
    cudaGetSymbolAddress((void**)&csr,   g_csr);
    cudaGetSymbolAddress((void**)&flag,  g_flag);
    cudaGetSymbolAddress((void**)&pval,  g_pval);
    cudaGetSymbolAddress((void**)&ival,  g_ival);
    cudaGetSymbolAddress((void**)&pbuf,  g_proj);

    float* z     = (float*)d_out;
    float* probs = (float*)d_out + (size_t)n * HH;

    const int nb    = cdiv(n, 1024);              // 98 (<=128)
    const int gGemm = cdiv(n, 128);
    const int gScat = cdiv(nEp > nEn ? nEp : nEn, 256);
    const int gAgg  = cdiv(n, 8);

    // 1) zero counts + lookback flags
    zero_kernel<<<cdiv(n + 256, 256), 256>>>((int4*)cnt, flag, n);
    // 2) degrees (all 4 arrays)
    deg4_kernel<<<dim3(cdiv(nEp, 256), 4), 256>>>(srcp, dstp, srcn, dstn, cnt, n, nEp);
    // 3) norms + CSR offsets in one launch (decoupled lookback)
    scan_lb_norm<<<dim3(nb, 4), 256>>>(cnt, norms, flag, pval, ival, off, cur,
                                       n, nEp, nEn);
    // 4) layer-1 GEMM (tensor cores) overlapped with CSR scatter
    gemm1_scatter<<<2 * gGemm + 2 * gScat, 256>>>(
        x, norms, W0p, W0n, y, srcp, dstp, srcn, dstn, cur, csr,
        n, nEp, nEn, gGemm, gScat);
    // 5) layer-1 aggregation fused with layer-2 GEMM  (reads y, writes y2)
    agg1_gemm2<<<dim3(gGemm, 2), 256>>>(y, off, csr, norms, b0p, b0n,
                                        W1p, W1n, y2, n);
    // 6) layer-2 aggregation + combine + classifier projection (reads y2)
    agg_l2<<<gAgg, 256>>>(y2, off, csr, norms, b1p, b1n, Wc, z, pbuf, n);
    // 7) classifier
    cls_kernel<<<cdiv(nQ, 256), 256>>>(pbuf, ei, bc, probs, nQ);
}

// round 10
// speedup vs baseline: 1.3239x; 1.3239x over previous
#include <cuda_runtime.h>
#include <cuda_fp16.h>
#include <mma.h>
#include <math.h>

using namespace nvcuda;

#define NN 100000
#define EE 1600000
#define HH 64
#define XS_LD 80   // padded smem stride (halves / floats)

typedef unsigned long long u64;

// ---------------- scratch (device globals) ----------------------------------
__device__ __half g_y[2 * (size_t)NN * HH];  // GEMM outputs (fp16)
__device__ __half g_h[2 * (size_t)NN * HH];  // layer-1 activations (fp16)
__device__ float  g_norms[4 * NN];           // csp | cdp | csn | cdn
__device__ int    g_cnt[4 * NN];             // int degree counts (same layout)
__device__ int    g_off[2 * (NN + 1)];       // CSR row offsets (dst) per relation
__device__ int    g_cur[2 * NN];             // scatter cursors
__device__ int    g_csr[2 * EE];             // src ids grouped by dst
__device__ int    g_flag[2 * 128];           // lookback flags (0/1/2)
__device__ int    g_pval[2 * 128];           // block partial sums
__device__ int    g_ival[2 * 128];           // block inclusive prefixes
__device__ float  g_proj[4 * NN];            // classifier projections [N][4]

// ---------------- utility ----------------------------------------------------
__global__ void zero_kernel(int4* __restrict__ cnt4, int* __restrict__ flag, int n) {
    int t = blockIdx.x * blockDim.x + threadIdx.x;
    if (t < n) cnt4[t] = make_int4(0, 0, 0, 0);
    else if (t < n + 256) flag[t - n] = 0;
}

__global__ void deg4_kernel(const int* __restrict__ sp, const int* __restrict__ dp,
                            const int* __restrict__ sn, const int* __restrict__ dn,
                            int* __restrict__ cnt, int n, int nE) {
    int t = blockIdx.x * blockDim.x + threadIdx.x;
    if (t >= nE) return;
    int w = blockIdx.y;
    const int* idx = (w == 0) ? sp : (w == 1) ? dp : (w == 2) ? sn : dn;
    atomicAdd(cnt + (size_t)w * n + idx[t], 1);
}

// ---------------- one-launch scan: norms (all 4) + CSR offsets (lookback) ----
__global__ void scan_lb_norm(const int* __restrict__ cnt, float* __restrict__ norms,
                             volatile int* flag, volatile int* pval, volatile int* ival,
                             int* __restrict__ offv, int* __restrict__ cur,
                             int n, int nEp, int nEn) {
    int w = blockIdx.y;                 // 0..3
    int bx = blockIdx.x;
    int tid = threadIdx.x;
    const int* c = cnt + (size_t)w * n;
    float* nm = norms + (size_t)w * n;
    int base = bx * 1024 + tid * 4;

    int v[4], s = 0;
    #pragma unroll
    for (int j = 0; j < 4; j++) {
        int i = base + j;
        v[j] = (i < n) ? c[i] : 0;
        s += v[j];
        if (i < n) nm[i] = (v[j] > 0) ? rsqrtf((float)v[j]) : 0.f;
    }
    if (!(w & 1)) return;               // only dst arrays build CSR
    int rel = w >> 1;
    int sbase = rel * 128;

    __shared__ int sm[256];
    sm[tid] = s; __syncthreads();
    for (int ofs = 1; ofs < 256; ofs <<= 1) {
        int a = (tid >= ofs) ? sm[tid - ofs] : 0;
        __syncthreads();
        sm[tid] += a;
        __syncthreads();
    }
    int excl = sm[tid] - s;
    int bsum = sm[255];

    __shared__ int bprefix;
    if (tid == 0) {
        pval[sbase + bx] = bsum;
        __threadfence();
        flag[sbase + bx] = 1;
        int pref = 0;
        for (int p = bx - 1; p >= 0; ) {
            int f;
            do { f = flag[sbase + p]; } while (f == 0);
            if (f == 2) { pref += ival[sbase + p]; break; }
            pref += pval[sbase + p];
            p--;
        }
        ival[sbase + bx] = pref + bsum;
        __threadfence();
        flag[sbase + bx] = 2;
        bprefix = pref;
    }
    __syncthreads();

    int ex = bprefix + excl;
    int* o  = offv + (size_t)rel * (n + 1);
    int* cu = cur + (size_t)rel * n;
    #pragma unroll
    for (int j = 0; j < 4; j++) {
        int i = base + j;
        if (i < n) { o[i] = ex; cu[i] = ex; }
        ex += v[j];
    }
    if (bx == 0 && tid == 0) o[n] = rel ? nEn : nEp;
}

// ---------------- wmma GEMM body with smem union (40 KB total) ---------------
// block = 256 threads (8 warps); warp computes 16 rows x 64 cols.
// Layout: [ Wh 10240B | Xh 20480B ] unioned with [ Os 40960B ] (after MMA).
template <typename T>
__device__ __forceinline__ void gemm_body(const T* __restrict__ X,
                                          const float* __restrict__ cs,
                                          const float* __restrict__ W,
                                          __half* __restrict__ Yo, int n, int blk) {
    __shared__ __align__(16) float sbuf[128 * XS_LD];   // 40960 B
    __half* Wh = (__half*)sbuf;                  // 64*XS_LD halves
    __half* Xh = ((__half*)sbuf) + 64 * XS_LD;   // 128*XS_LD halves
    float*  Os = sbuf;                           // reused after MMA

    int tid = threadIdx.x;
    int row0 = blk * 128;

    for (int i = tid; i < 2048; i += 256) {
        int k = i >> 5, j = i & 31;
        float2 v = ((const float2*)W)[(size_t)k * 32 + j];
        *(__half2*)&Wh[k * XS_LD + 2 * j] = __floats2half2_rn(v.x, v.y);
    }
    if (sizeof(T) == 4) {        // fp32 input
        const float* Xf = (const float*)X;
        for (int i = tid; i < 2048; i += 256) {
            int r = i >> 4, kq = i & 15;
            int gr = row0 + r;
            float4 v = (gr < n) ? ((const float4*)Xf)[(size_t)gr * 16 + kq]
                                : make_float4(0.f, 0.f, 0.f, 0.f);
            *(__half2*)&Xh[r * XS_LD + 4 * kq + 0] = __floats2half2_rn(v.x, v.y);
            *(__half2*)&Xh[r * XS_LD + 4 * kq + 2] = __floats2half2_rn(v.z, v.w);
        }
    } else {                     // fp16 input
        const __half* Xq = (const __half*)X;
        for (int i = tid; i < 2048; i += 256) {
            int r = i >> 4, kq = i & 15;
            int gr = row0 + r;
            uint2 v2 = (gr < n) ? __ldg((const uint2*)Xq + (size_t)gr * 16 + kq)
                                : make_uint2(0, 0);
            *(uint2*)&Xh[r * XS_LD + 4 * kq] = v2;
        }
    }
    __syncthreads();

    int w = tid >> 5;
    wmma::fragment<wmma::accumulator, 16, 16, 16, float> acc[4];
    #pragma unroll
    for (int t = 0; t < 4; t++) wmma::fill_fragment(acc[t], 0.f);
    #pragma unroll
    for (int k = 0; k < 64; k += 16) {
        wmma::fragment<wmma::matrix_a, 16, 16, 16, __half, wmma::row_major> a;
        wmma::load_matrix_sync(a, &Xh[(w * 16) * XS_LD + k], XS_LD);
        #pragma unroll
        for (int t = 0; t < 4; t++) {
            wmma::fragment<wmma::matrix_b, 16, 16, 16, __half, wmma::row_major> b;
            wmma::load_matrix_sync(b, &Wh[k * XS_LD + t * 16], XS_LD);
            wmma::mma_sync(acc[t], a, b, acc[t]);
        }
    }
    __syncthreads();             // all reads of Wh/Xh done; Os may overwrite
    #pragma unroll
    for (int t = 0; t < 4; t++)
        wmma::store_matrix_sync(&Os[(w * 16) * XS_LD + t * 16], acc[t], XS_LD,
                                wmma::mem_row_major);
    __syncthreads();

    for (int i = tid; i < 2048; i += 256) {
        int r = i >> 4, q = i & 15;
        int gr = row0 + r;
        if (gr >= n) continue;
        float c = cs[gr];
        float4 v = *(const float4*)&Os[r * XS_LD + 4 * q];
        __half2 o[2] = {__floats2half2_rn(v.x * c, v.y * c),
                        __floats2half2_rn(v.z * c, v.w * c)};
        *(uint2*)(Yo + (size_t)gr * 64 + 4 * q) = *(const uint2*)o;
    }
}

// ---------------- fat kernel: layer-1 GEMM (both rels) + CSR scatter ---------
__global__ void __launch_bounds__(256, 4)
gemm1_scatter(const float* __restrict__ x, const float* __restrict__ norms,
              const float* __restrict__ W0, const float* __restrict__ W1,
              __half* __restrict__ Y,
              const int* __restrict__ srcp, const int* __restrict__ dstp,
              const int* __restrict__ srcn, const int* __restrict__ dstn,
              int* __restrict__ cur, int* __restrict__ csr,
              int n, int nEp, int nEn, int gGemm, int gScat) {
    int b = blockIdx.x;
    if (b < 2 * gGemm) {
        int rel = b / gGemm;
        gemm_body<float>(x, norms + 2 * (size_t)rel * n,
                         rel ? W1 : W0, Y + (size_t)rel * n * 64, n, b % gGemm);
    } else {
        int sb = b - 2 * gGemm;
        int rel = sb / gScat;
        int e = (sb % gScat) * 256 + threadIdx.x;
        int nE = rel ? nEn : nEp;
        if (e >= nE) return;
        const int* src = rel ? srcn : srcp;
        const int* dst = rel ? dstn : dstp;
        int d = dst[e];
        int p = atomicAdd(cur + (size_t)rel * n + d, 1);
        csr[(size_t)rel * EE + p] = src[e];
    }
}

// ---------------- layer-2 GEMM (fp16 input) ----------------------------------
__global__ void __launch_bounds__(256, 4)
gemm_l2(const __half* __restrict__ h, const float* __restrict__ norms,
        const float* __restrict__ W0, const float* __restrict__ W1,
        __half* __restrict__ Y, int n) {
    int rel = blockIdx.y;
    gemm_body<__half>(h + (size_t)rel * n * 64, norms + 2 * (size_t)rel * n,
                      rel ? W1 : W0, Y + (size_t)rel * n * 64, n, blockIdx.x);
}

// ---------------- CSR pull (fp16 payload, fp32 accum, MLP=4) -----------------
__device__ __forceinline__ float2 csr_sum(const int* __restrict__ off,
                                          const int* __restrict__ csr,
                                          const __half2* __restrict__ ylane, int node) {
    int j = off[node], end = off[node + 1];
    float2 a0 = make_float2(0.f, 0.f), a1 = make_float2(0.f, 0.f);
    float2 a2 = make_float2(0.f, 0.f), a3 = make_float2(0.f, 0.f);
    for (; j + 4 <= end; j += 4) {
        int s0 = __ldg(csr + j + 0);
        int s1 = __ldg(csr + j + 1);
        int s2 = __ldg(csr + j + 2);
        int s3 = __ldg(csr + j + 3);
        __half2 h0 = __ldg(ylane + (size_t)s0 * 32);
        __half2 h1 = __ldg(ylane + (size_t)s1 * 32);
        __half2 h2 = __ldg(ylane + (size_t)s2 * 32);
        __half2 h3 = __ldg(ylane + (size_t)s3 * 32);
        float2 v0 = __half22float2(h0); a0.x += v0.x; a0.y += v0.y;
        float2 v1 = __half22float2(h1); a1.x += v1.x; a1.y += v1.y;
        float2 v2 = __half22float2(h2); a2.x += v2.x; a2.y += v2.y;
        float2 v3 = __half22float2(h3); a3.x += v3.x; a3.y += v3.y;
    }
    for (; j < end; j++) {
        int s = __ldg(csr + j);
        float2 v = __half22float2(__ldg(ylane + (size_t)s * 32));
        a0.x += v.x; a0.y += v.y;
    }
    a0.x += a1.x; a0.y += a1.y;
    a2.x += a3.x; a2.y += a3.y;
    a0.x += a2.x; a0.y += a2.y;
    return a0;
}

// layer 1: h_rel[i,:] = half(relu(c_dst[i] * sum y_rel[src] + b0_rel))
__global__ void agg_l1(const __half* __restrict__ y, const int* __restrict__ off,
                       const int* __restrict__ csr, const float* __restrict__ norms,
                       const float* __restrict__ b0p, const float* __restrict__ b0n,
                       __half* __restrict__ h, int n) {
    int rel = blockIdx.y;
    int node = blockIdx.x * 8 + (threadIdx.x >> 5);
    if (node >= n) return;
    int lane = threadIdx.x & 31;
    const __half2* yl = (const __half2*)(y + (size_t)rel * n * 64) + lane;
    float2 a = csr_sum(off + (size_t)rel * (n + 1), csr + (size_t)rel * EE, yl, node);
    float c = norms[(size_t)(1 + 2 * rel) * n + node];
    const float* b = rel ? b0n : b0p;
    float rx = fmaxf(c * a.x + b[2 * lane + 0], 0.f);
    float ry = fmaxf(c * a.y + b[2 * lane + 1], 0.f);
    ((__half2*)(h + (size_t)rel * n * 64 + (size_t)node * 64))[lane] =
        __floats2half2_rn(rx, ry);
}

// layer 2 agg fused: z = relu(cdp*sumP + b1p) - relu(cdn*sumN + b1n) + proj
__global__ void agg_l2(const __half* __restrict__ y, const int* __restrict__ off,
                       const int* __restrict__ csr, const float* __restrict__ norms,
                       const float* __restrict__ b1p, const float* __restrict__ b1n,
                       const float* __restrict__ Wc,
                       float* __restrict__ z, float* __restrict__ proj, int n) {
    __shared__ float Wcs[256];
    Wcs[threadIdx.x] = Wc[threadIdx.x];   // blockDim == 256
    __syncthreads();

    int node = blockIdx.x * 8 + (threadIdx.x >> 5);
    if (node >= n) return;
    int lane = threadIdx.x & 31;
    const __half2* ylP = (const __half2*)y + lane;
    const __half2* ylN = (const __half2*)(y + (size_t)n * 64) + lane;
    float2 aP = csr_sum(off, csr, ylP, node);
    float2 aN = csr_sum(off + (n + 1), csr + (size_t)EE, ylN, node);
    float cp = norms[(size_t)n + node];
    float cn = norms[3 * (size_t)n + node];
    float2 r;
    r.x = fmaxf(cp * aP.x + b1p[2 * lane + 0], 0.f) - fmaxf(cn * aN.x + b1n[2 * lane + 0], 0.f);
    r.y = fmaxf(cp * aP.y + b1p[2 * lane + 1], 0.f) - fmaxf(cn * aN.y + b1n[2 * lane + 1], 0.f);
    *(float2*)(z + (size_t)node * 64 + lane * 2) = r;

    int k = 2 * lane;
    float s0 = r.x * Wcs[k * 2 + 0] + r.y * Wcs[(k + 1) * 2 + 0];
    float s1 = r.x * Wcs[k * 2 + 1] + r.y * Wcs[(k + 1) * 2 + 1];
    float d0 = r.x * Wcs[128 + k * 2 + 0] + r.y * Wcs[128 + (k + 1) * 2 + 0];
    float d1 = r.x * Wcs[128 + k * 2 + 1] + r.y * Wcs[128 + (k + 1) * 2 + 1];
    #pragma unroll
    for (int o = 16; o > 0; o >>= 1) {
        s0 += __shfl_xor_sync(0xffffffffu, s0, o);
        s1 += __shfl_xor_sync(0xffffffffu, s1, o);
        d0 += __shfl_xor_sync(0xffffffffu, d0, o);
        d1 += __shfl_xor_sync(0xffffffffu, d1, o);
    }
    if (lane == 0) ((float4*)proj)[node] = make_float4(s0, s1, d0, d1);
}

// ---------------- classifier --------------------------------------------------
__global__ void cls_kernel(const float* __restrict__ p, const int* __restrict__ ei,
                           const float* __restrict__ bc, float* __restrict__ out, int nQ) {
    int q = blockIdx.x * blockDim.x + threadIdx.x;
    if (q >= nQ) return;
    int s = __ldg(ei + q);
    int d = __ldg(ei + nQ + q);
    float4 ps = ((const float4*)p)[s];
    float4 pd = ((const float4*)p)[d];
    float l0 = ps.x + pd.z + bc[0];
    float l1 = ps.y + pd.w + bc[1];
    float2 o;
    o.x = 1.f / (1.f + __expf(-l0));
    o.y = 1.f / (1.f + __expf(-l1));
    ((float2*)out)[q] = o;
}

// ---------------- launch -------------------------------------------------------
static inline int cdiv(long long a, int b) { return (int)((a + b - 1) / b); }

extern "C" void kernel_launch(void* const* d_in, const int* in_sizes, int n_in,
                              void* d_out, int out_size) {
    const float* x    = (const float*)d_in[0];
    const float* W0p  = (const float*)d_in[1];
    const float* b0p  = (const float*)d_in[2];
    const float* W0n  = (const float*)d_in[3];
    const float* b0n  = (const float*)d_in[4];
    const float* W1p  = (const float*)d_in[5];
    const float* b1p  = (const float*)d_in[6];
    const float* W1n  = (const float*)d_in[7];
    const float* b1n  = (const float*)d_in[8];
    const float* Wc   = (const float*)d_in[9];
    const float* bc   = (const float*)d_in[10];
    const int*   srcp = (const int*)d_in[11];
    const int*   dstp = (const int*)d_in[12];
    const int*   srcn = (const int*)d_in[13];
    const int*   dstn = (const int*)d_in[14];
    const int*   ei   = (const int*)d_in[15];

    const int n   = in_sizes[0] / HH;
    const int nEp = in_sizes[11];
    const int nEn = in_sizes[13];
    const int nQ  = in_sizes[15] / 2;

    __half *y, *h;
    float *norms, *pbuf;
    int *cnt, *off, *cur, *csr, *flag, *pval, *ival;
    cudaGetSymbolAddress((void**)&y,     g_y);
    cudaGetSymbolAddress((void**)&h,     g_h);
    cudaGetSymbolAddress((void**)&norms, g_norms);
    cudaGetSymbolAddress((void**)&cnt,   g_cnt);
    cudaGetSymbolAddress((void**)&off,   g_off);
    cudaGetSymbolAddress((void**)&cur,   g_cur);
    cudaGetSymbolAddress((void**)&csr,   g_csr);
    cudaGetSymbolAddress((void**)&flag,  g_flag);
    cudaGetSymbolAddress((void**)&pval,  g_pval);
    cudaGetSymbolAddress((void**)&ival,  g_ival);
    cudaGetSymbolAddress((void**)&pbuf,  g_proj);

    float* z     = (float*)d_out;
    float* probs = (float*)d_out + (size_t)n * HH;

    const int nb    = cdiv(n, 1024);              // 98 (<=128)
    const int gGemm = cdiv(n, 128);
    const int gScat = cdiv(nEp > nEn ? nEp : nEn, 256);
    const int gAgg  = cdiv(n, 8);

    // 1) zero counts + lookback flags
    zero_kernel<<<cdiv(n + 256, 256), 256>>>((int4*)cnt, flag, n);
    // 2) degrees (all 4 arrays)
    deg4_kernel<<<dim3(cdiv(nEp, 256), 4), 256>>>(srcp, dstp, srcn, dstn, cnt, n, nEp);
    // 3) norms + CSR offsets in one launch (decoupled lookback)
    scan_lb_norm<<<dim3(nb, 4), 256>>>(cnt, norms, flag, pval, ival, off, cur,
                                       n, nEp, nEn);
    // 4) layer-1 GEMM (tensor cores) overlapped with CSR scatter
    gemm1_scatter<<<2 * gGemm + 2 * gScat, 256>>>(
        x, norms, W0p, W0n, y, srcp, dstp, srcn, dstn, cur, csr,
        n, nEp, nEn, gGemm, gScat);
    // 5) layer-1 aggregation -> h (fp16), full occupancy
    agg_l1<<<dim3(gAgg, 2), 256>>>(y, off, csr, norms, b0p, b0n, h, n);
    // 6) layer-2 GEMM (fp16 input, tensor cores)
    gemm_l2<<<dim3(gGemm, 2), 256>>>(h, norms, W1p, W1n, y, n);
    // 7) layer-2 aggregation + combine + classifier projection
    agg_l2<<<gAgg, 256>>>(y, off, csr, norms, b1p, b1n, Wc, z, pbuf, n);
    // 8) classifier
    cls_kernel<<<cdiv(nQ, 256), 256>>>(pbuf, ei, bc, probs, nQ);
}